// round 3
// baseline (speedup 1.0000x reference)
#include <cuda_runtime.h>
#include <math.h>

// ---------------------------------------------------------------------------
// DensityNet: edge-based RBF convolution (hat basis, polar), scatter-add.
// R3: no warp scan (plain RED.ADD), shared-mem paired W, 2 edges/thread.
// ---------------------------------------------------------------------------

#define NRBF 8
#define INV_HAT_WIDTH 3.5f

__global__ void zero_kernel4(float4* out, int n4) {
    int i = blockIdx.x * blockDim.x + threadIdx.x;
    if (i < n4) out[i] = make_float4(0.f, 0.f, 0.f, 0.f);
}

// atan2(y,x)/pi via octant reduction + odd minimax poly (abs err ~3e-6)
__device__ __forceinline__ float atan2_over_pi(float y, float x) {
    float ax = fabsf(x), ay = fabsf(y);
    float mn = fminf(ax, ay), mx = fmaxf(ax, ay);
    float t  = __fdividef(mn, mx);
    float t2 = t * t;
    float p = 0.00663147f;
    p = fmaf(p, t2, -0.0270968f);
    p = fmaf(p, t2,  0.0573382f);
    p = fmaf(p, t2, -0.1051301f);
    p = fmaf(p, t2,  0.3182684f);
    float a = t * p;
    float v = (ay > ax) ? (0.5f - a) : a;
    if (x < 0.0f) v = 1.0f - v;
    return copysignf(v, y);
}

// one edge -> contribution value (shared W is paired float2 rows)
__device__ __forceinline__ float edge_val(
    float2 pq, float2 ps, float xj, float inv_support, const float2* sW)
{
    float dx = (ps.x - pq.x) * inv_support;
    float dy = (ps.y - pq.y) * inv_support;
    dx = fminf(fmaxf(dx, -1.0f), 1.0f);
    dy = fminf(fmaxf(dy, -1.0f), 1.0f);

    float d2 = fmaf(dx, dx, dy * dy);
    bool small = d2 < 1e-12f;

    float r   = small ? 0.0f : d2 * rsqrtf(d2);
    float ddx = small ? 1.0f : dx;
    float ddy = small ? 0.0f : dy;

    // hat over u = 2r-1:  p = (u+1)*3.5 = 7r
    float pu = 7.0f * r;
    int ia = min((int)pu, NRBF - 2);
    float fa = fminf(pu - (float)ia, 1.0f);

    float v = atan2_over_pi(ddy, ddx);
    float pv = (v + 1.0f) * INV_HAT_WIDTH;
    int ib = min((int)pv, NRBF - 2);
    float fb = fminf(fmaxf(pv - (float)ib, 0.0f), 1.0f);

    float omr  = 1.0f - r;
    float omr2 = omr * omr;
    float win  = fmaxf(omr2 * omr2 * fmaf(4.0f, r, 1.0f), 0.0f);

    float2 w0 = sW[ia * NRBF + ib];
    float2 w1 = sW[(ia + 1) * NRBF + ib];
    float a0 = 1.0f - fa, b0 = 1.0f - fb;
    float w = a0 * fmaf(fb, w0.y, b0 * w0.x)
            + fa * fmaf(fb, w1.y, b0 * w1.x);

    return w * win * xj;
}

__global__ void edge_conv2_kernel(
    const float2* __restrict__ posQ,
    const float2* __restrict__ posS,
    const float*  __restrict__ featS,
    const int*    __restrict__ ei,
    const int*    __restrict__ ej,
    const float*  __restrict__ W,
    const float*  __restrict__ support_ptr,
    int E,
    float* __restrict__ out)
{
    __shared__ float2 sW[NRBF * NRBF];   // paired rows: {W[i][j], W[i][j+1]}
    {
        int t = threadIdx.x;
        if (t < NRBF * NRBF) {
            int j = t & (NRBF - 1);
            float a = __ldg(&W[t]);
            float b = (j < NRBF - 1) ? __ldg(&W[t + 1]) : 0.0f;
            sW[t] = make_float2(a, b);
        }
    }
    __syncthreads();

    const int t = blockIdx.x * blockDim.x + threadIdx.x;
    const int e0 = 2 * t;
    if (e0 >= E) return;

    const float inv_support = __fdividef(1.0f, support_ptr[0]);

    if (e0 + 1 < E) {
        // vectorized pair
        int2 qi2 = __ldg((const int2*)ei + t);
        int2 sj2 = __ldg((const int2*)ej + t);

        float2 pq0 = posQ[qi2.x];
        float2 ps0 = posS[sj2.x];
        float  x0  = __ldg(&featS[sj2.x]);
        float2 pq1 = posQ[qi2.y];
        float2 ps1 = posS[sj2.y];
        float  x1  = __ldg(&featS[sj2.y]);

        float v0 = edge_val(pq0, ps0, x0, inv_support, sW);
        float v1 = edge_val(pq1, ps1, x1, inv_support, sW);

        if (qi2.x == qi2.y) {
            atomicAdd(&out[qi2.x], v0 + v1);
        } else {
            atomicAdd(&out[qi2.x], v0);
            atomicAdd(&out[qi2.y], v1);
        }
    } else {
        // tail single edge
        int qi = __ldg(&ei[e0]);
        int sj = __ldg(&ej[e0]);
        float v = edge_val(posQ[qi], posS[sj], __ldg(&featS[sj]), inv_support, sW);
        atomicAdd(&out[qi], v);
    }
}

extern "C" void kernel_launch(void* const* d_in, const int* in_sizes, int n_in,
                              void* d_out, int out_size) {
    const float2* fluidPos    = (const float2*)d_in[0];
    const float2* boundaryPos = (const float2*)d_in[1];
    const float*  fluidFeat   = (const float*)d_in[2];
    const float*  boundFeat   = (const float*)d_in[3];
    const float*  Wf          = (const float*)d_in[4];
    const float*  Wb          = (const float*)d_in[5];
    const float*  support     = (const float*)d_in[6];
    const int*    fi          = (const int*)d_in[7];
    const int*    fj          = (const int*)d_in[8];
    const int*    bf          = (const int*)d_in[9];
    const int*    bb          = (const int*)d_in[10];

    float* out = (float*)d_out;
    const int Ef = in_sizes[7];
    const int Eb = in_sizes[9];

    {
        int n4 = out_size / 4;
        int threads = 256;
        int blocks = (n4 + threads - 1) / threads;
        zero_kernel4<<<blocks, threads>>>((float4*)out, n4);
    }

    const int threads = 256;
    if (Ef > 0) {
        int nt = (Ef + 1) / 2;
        int blocks = (nt + threads - 1) / threads;
        edge_conv2_kernel<<<blocks, threads>>>(
            fluidPos, fluidPos, fluidFeat, fi, fj, Wf, support, Ef, out);
    }
    if (Eb > 0) {
        int nt = (Eb + 1) / 2;
        int blocks = (nt + threads - 1) / threads;
        edge_conv2_kernel<<<blocks, threads>>>(
            fluidPos, boundaryPos, boundFeat, bf, bb, Wb, support, Eb, out);
    }
}

// round 4
// speedup vs baseline: 1.0264x; 1.0264x over previous
#include <cuda_runtime.h>
#include <math.h>

// ---------------------------------------------------------------------------
// DensityNet: fused dual RBF edge convolution.
// R4 = R2 structure + match_any-based segmented reduction + shared-mem W.
// ---------------------------------------------------------------------------

#define NRBF 8
#define INV_HAT_WIDTH 3.5f

__global__ void zero_kernel4(float4* out, int n4) {
    int i = blockIdx.x * blockDim.x + threadIdx.x;
    if (i < n4) out[i] = make_float4(0.f, 0.f, 0.f, 0.f);
}

// atan2(y,x)/pi via octant reduction + odd minimax poly (abs err ~3e-6)
__device__ __forceinline__ float atan2_over_pi(float y, float x) {
    float ax = fabsf(x), ay = fabsf(y);
    float mn = fminf(ax, ay), mx = fmaxf(ax, ay);
    float t  = __fdividef(mn, mx);
    float t2 = t * t;
    float p = 0.00663147f;
    p = fmaf(p, t2, -0.0270968f);
    p = fmaf(p, t2,  0.0573382f);
    p = fmaf(p, t2, -0.1051301f);
    p = fmaf(p, t2,  0.3182684f);
    float a = t * p;
    float v = (ay > ax) ? (0.5f - a) : a;
    if (x < 0.0f) v = 1.0f - v;
    return copysignf(v, y);
}

__global__ void fused_edge_kernel(
    const float2* __restrict__ fluidPos,
    const float2* __restrict__ boundaryPos,
    const float*  __restrict__ fluidFeat,
    const float*  __restrict__ boundFeat,
    const int*    __restrict__ fi, const int* __restrict__ fj,
    const int*    __restrict__ bf, const int* __restrict__ bb,
    const float*  __restrict__ Wf, const float* __restrict__ Wb,
    const float*  __restrict__ support_ptr,
    int Ef, int Etot,
    float* __restrict__ out)
{
    // paired W rows for both tables: sW[t] = {W[i][j], W[i][j+1]}
    __shared__ float2 sW[2 * NRBF * NRBF];
    {
        int t = threadIdx.x;
        if (t < 2 * NRBF * NRBF) {
            const float* Wsrc = (t < NRBF * NRBF) ? Wf : Wb;
            int idx = t & (NRBF * NRBF - 1);
            int j = idx & (NRBF - 1);
            float a = __ldg(&Wsrc[idx]);
            float b = (j < NRBF - 1) ? __ldg(&Wsrc[idx + 1]) : 0.0f;
            sW[t] = make_float2(a, b);
        }
    }
    __syncthreads();

    const unsigned FULL = 0xffffffffu;
    const int e = blockIdx.x * blockDim.x + threadIdx.x;
    const int lane = threadIdx.x & 31;

    float val = 0.0f;
    int qi = -1;

    if (e < Etot) {
        const bool isF = (e < Ef);
        const int ee = isF ? e : (e - Ef);
        const int*    EI = isF ? fi : bf;
        const int*    EJ = isF ? fj : bb;
        const float2* PS = isF ? fluidPos : boundaryPos;
        const float*  FS = isF ? fluidFeat : boundFeat;
        const int     wbase = isF ? 0 : NRBF * NRBF;

        qi = __ldg(&EI[ee]);
        const int sj = __ldg(&EJ[ee]);

        const float inv_support = __fdividef(1.0f, support_ptr[0]);
        const float2 pq = fluidPos[qi];
        const float2 ps = PS[sj];

        float dx = (ps.x - pq.x) * inv_support;
        float dy = (ps.y - pq.y) * inv_support;
        dx = fminf(fmaxf(dx, -1.0f), 1.0f);
        dy = fminf(fmaxf(dy, -1.0f), 1.0f);

        const float d2 = fmaf(dx, dx, dy * dy);
        const bool small = d2 < 1e-12f;

        const float r   = small ? 0.0f : d2 * rsqrtf(d2);
        const float ddx = small ? 1.0f : dx;
        const float ddy = small ? 0.0f : dy;

        // hat over u = 2r-1: p = (u+1)*3.5 = 7r
        const float pu = 7.0f * r;
        int ia = min((int)pu, NRBF - 2);
        const float fa = fminf(pu - (float)ia, 1.0f);

        const float v  = atan2_over_pi(ddy, ddx);
        const float pv = (v + 1.0f) * INV_HAT_WIDTH;
        int ib = min((int)pv, NRBF - 2);
        const float fb = fminf(fmaxf(pv - (float)ib, 0.0f), 1.0f);

        const float omr  = 1.0f - r;
        const float omr2 = omr * omr;
        const float win  = fmaxf(omr2 * omr2 * fmaf(4.0f, r, 1.0f), 0.0f);

        const float xj = __ldg(&FS[sj]);

        const float2 w0 = sW[wbase + ia * NRBF + ib];
        const float2 w1 = sW[wbase + (ia + 1) * NRBF + ib];
        const float a0 = 1.0f - fa, b0 = 1.0f - fb;
        const float w = a0 * fmaf(fb, w0.y, b0 * w0.x)
                      + fa * fmaf(fb, w1.y, b0 * w1.x);

        val = w * win * xj;
    }

    // segmented warp reduction over equal-qi runs using match mask.
    const unsigned mask = __match_any_sync(FULL, qi);
    #pragma unroll
    for (int off = 1; off < 32; off <<= 1) {
        float ov = __shfl_down_sync(FULL, val, off);
        unsigned pos = (unsigned)lane + (unsigned)off;
        if (pos < 32u && ((mask >> pos) & 1u)) val += ov;
    }
    // head lane: no lower lane shares this qi
    const bool head = ((mask & ((1u << lane) - 1u)) == 0u);
    if (head && qi >= 0) atomicAdd(&out[qi], val);
}

extern "C" void kernel_launch(void* const* d_in, const int* in_sizes, int n_in,
                              void* d_out, int out_size) {
    const float2* fluidPos    = (const float2*)d_in[0];
    const float2* boundaryPos = (const float2*)d_in[1];
    const float*  fluidFeat   = (const float*)d_in[2];
    const float*  boundFeat   = (const float*)d_in[3];
    const float*  Wf          = (const float*)d_in[4];
    const float*  Wb          = (const float*)d_in[5];
    const float*  support     = (const float*)d_in[6];
    const int*    fi          = (const int*)d_in[7];
    const int*    fj          = (const int*)d_in[8];
    const int*    bf          = (const int*)d_in[9];
    const int*    bb          = (const int*)d_in[10];

    float* out = (float*)d_out;
    const int Ef = in_sizes[7];
    const int Eb = in_sizes[9];
    const int Etot = Ef + Eb;

    {
        int n4 = out_size / 4;
        int threads = 256;
        int blocks = (n4 + threads - 1) / threads;
        zero_kernel4<<<blocks, threads>>>((float4*)out, n4);
    }

    if (Etot > 0) {
        int threads = 256;
        int blocks = (Etot + threads - 1) / threads;
        fused_edge_kernel<<<blocks, threads>>>(
            fluidPos, boundaryPos, fluidFeat, boundFeat,
            fi, fj, bf, bb, Wf, Wb, support, Ef, Etot, out);
    }
}

// round 5
// speedup vs baseline: 1.2830x; 1.2500x over previous
#include <cuda_runtime.h>
#include <math.h>

// ---------------------------------------------------------------------------
// DensityNet R5: fused dual RBF edge conv.
//  - prep kernel packs (pos, feat) -> float4 scratch + zeros output
//  - edge kernel: 1 x LDG.128 gather per source, ballot-based segmented
//    warp reduction, __ldg weight table.
// ---------------------------------------------------------------------------

#define NRBF 8
#define INV_HAT_WIDTH 3.5f
#define MAX_NF 65536
#define MAX_NB 8192

__device__ float4 g_srcF[MAX_NF];
__device__ float4 g_srcB[MAX_NB];

__global__ void prep_kernel(
    const float2* __restrict__ fluidPos,  const float* __restrict__ fluidFeat,  int nf,
    const float2* __restrict__ boundPos,  const float* __restrict__ boundFeat,  int nb,
    float* __restrict__ out, int nout)
{
    int i = blockIdx.x * blockDim.x + threadIdx.x;
    if (i < nf) {
        float2 p = fluidPos[i];
        g_srcF[i] = make_float4(p.x, p.y, fluidFeat[i], 0.0f);
    }
    if (i < nb) {
        float2 p = boundPos[i];
        g_srcB[i] = make_float4(p.x, p.y, boundFeat[i], 0.0f);
    }
    if (i < nout) out[i] = 0.0f;
}

// atan2(y,x)/pi via octant reduction + odd minimax poly (abs err ~3e-6)
__device__ __forceinline__ float atan2_over_pi(float y, float x) {
    float ax = fabsf(x), ay = fabsf(y);
    float mn = fminf(ax, ay), mx = fmaxf(ax, ay);
    float t  = __fdividef(mn, mx);
    float t2 = t * t;
    float p = 0.00663147f;
    p = fmaf(p, t2, -0.0270968f);
    p = fmaf(p, t2,  0.0573382f);
    p = fmaf(p, t2, -0.1051301f);
    p = fmaf(p, t2,  0.3182684f);
    float a = t * p;
    float v = (ay > ax) ? (0.5f - a) : a;
    if (x < 0.0f) v = 1.0f - v;
    return copysignf(v, y);
}

__global__ void fused_edge_kernel(
    const float2* __restrict__ fluidPos,
    const int*    __restrict__ fi, const int* __restrict__ fj,
    const int*    __restrict__ bf, const int* __restrict__ bb,
    const float*  __restrict__ Wf, const float* __restrict__ Wb,
    const float*  __restrict__ support_ptr,
    int Ef, int Etot,
    float* __restrict__ out)
{
    const unsigned FULL = 0xffffffffu;
    const int e = blockIdx.x * blockDim.x + threadIdx.x;
    const int lane = threadIdx.x & 31;

    float val = 0.0f;
    int qi = -1;

    if (e < Etot) {
        const bool isF = (e < Ef);
        const int ee = isF ? e : (e - Ef);
        const int*    EI  = isF ? fi : bf;
        const int*    EJ  = isF ? fj : bb;
        const float4* SRC = isF ? g_srcF : g_srcB;
        const float*  WW  = isF ? Wf : Wb;

        qi = __ldg(&EI[ee]);
        const int sj = __ldg(&EJ[ee]);

        const float inv_support = __fdividef(1.0f, support_ptr[0]);
        const float2 pq = fluidPos[qi];
        const float4 src = SRC[sj];   // pos.x, pos.y, feat

        float dx = (src.x - pq.x) * inv_support;
        float dy = (src.y - pq.y) * inv_support;
        dx = fminf(fmaxf(dx, -1.0f), 1.0f);
        dy = fminf(fmaxf(dy, -1.0f), 1.0f);

        const float d2 = fmaf(dx, dx, dy * dy);
        const bool small = d2 < 1e-12f;

        const float r   = small ? 0.0f : d2 * rsqrtf(d2);
        const float ddx = small ? 1.0f : dx;
        const float ddy = small ? 0.0f : dy;

        // hat over u = 2r-1: p = (u+1)*3.5 = 7r
        const float pu = 7.0f * r;
        int ia = min((int)pu, NRBF - 2);
        const float fa = fminf(pu - (float)ia, 1.0f);

        const float v  = atan2_over_pi(ddy, ddx);
        const float pv = (v + 1.0f) * INV_HAT_WIDTH;
        int ib = min((int)pv, NRBF - 2);
        const float fb = fminf(fmaxf(pv - (float)ib, 0.0f), 1.0f);

        const float omr  = 1.0f - r;
        const float omr2 = omr * omr;
        const float win  = fmaxf(omr2 * omr2 * fmaf(4.0f, r, 1.0f), 0.0f);

        const float* Wr0 = WW + ia * NRBF + ib;
        const float* Wr1 = Wr0 + NRBF;
        const float a0 = 1.0f - fa, b0 = 1.0f - fb;
        const float w = a0 * fmaf(fb, __ldg(Wr0 + 1), b0 * __ldg(Wr0))
                      + fa * fmaf(fb, __ldg(Wr1 + 1), b0 * __ldg(Wr1));

        val = w * win * src.z;
    }

    // segmented warp suffix-sum over equal-qi runs (ballot head mask).
    const int qi_prev = __shfl_up_sync(FULL, qi, 1);
    const bool head = (lane == 0) || (qi_prev != qi);
    const unsigned hm = __ballot_sync(FULL, head);
    unsigned rest = (hm >> lane) >> 1;            // heads strictly above lane
    const int dist = rest ? __ffs(rest) : (32 - lane);  // run length from this lane

    #pragma unroll
    for (int off = 1; off < 32; off <<= 1) {
        float ov = __shfl_down_sync(FULL, val, off);
        if (off < dist) val += ov;
    }
    if (head && qi >= 0) atomicAdd(&out[qi], val);
}

extern "C" void kernel_launch(void* const* d_in, const int* in_sizes, int n_in,
                              void* d_out, int out_size) {
    const float2* fluidPos    = (const float2*)d_in[0];
    const float2* boundaryPos = (const float2*)d_in[1];
    const float*  fluidFeat   = (const float*)d_in[2];
    const float*  boundFeat   = (const float*)d_in[3];
    const float*  Wf          = (const float*)d_in[4];
    const float*  Wb          = (const float*)d_in[5];
    const float*  support     = (const float*)d_in[6];
    const int*    fi          = (const int*)d_in[7];
    const int*    fj          = (const int*)d_in[8];
    const int*    bf          = (const int*)d_in[9];
    const int*    bb          = (const int*)d_in[10];

    float* out = (float*)d_out;
    int nf = in_sizes[2];            // fluidFeatures element count = Nf
    int nb = in_sizes[3];            // boundaryFeatures element count = Nb
    if (nf > MAX_NF) nf = MAX_NF;
    if (nb > MAX_NB) nb = MAX_NB;
    const int Ef = in_sizes[7];
    const int Eb = in_sizes[9];
    const int Etot = Ef + Eb;

    {
        int n = out_size;
        if (nf > n) n = nf;
        if (nb > n) n = nb;
        int threads = 256;
        int blocks = (n + threads - 1) / threads;
        prep_kernel<<<blocks, threads>>>(fluidPos, fluidFeat, nf,
                                         boundaryPos, boundFeat, nb,
                                         out, out_size);
    }

    if (Etot > 0) {
        int threads = 256;
        int blocks = (Etot + threads - 1) / threads;
        fused_edge_kernel<<<blocks, threads>>>(
            fluidPos, fi, fj, bf, bb, Wf, Wb, support, Ef, Etot, out);
    }
}